// round 2
// baseline (speedup 1.0000x reference)
#include <cuda_runtime.h>

// LSTM seq2seq: encoder (1->64) over T=1000, decoder (1->65) with teacher
// forcing over T=1000, output Linear(65->1). B=2048.
//
// Design: persistent CTAs, each owns 13-14 batch rows for the entire scan.
// Thread t owns gate row t (weights in registers). Hidden/cell state in
// shared memory. Per step: gate phase (reg-weights x broadcast-h FMA),
// barrier, pointwise update (sigmoid/tanh), barrier, output projection.

#define T_STEPS   1000
#define BATCH     2048
#define NCTA      148
#define NTHREADS  256
#define NWARPS    (NTHREADS / 32)
#define BT_MAX    14
#define HP        68     // h/c row pitch (floats), 16B-aligned rows
#define GP        264    // gates row pitch (floats)

struct Smem {
    float h[BT_MAX * HP];
    float c[BT_MAX * HP];
    float gates[BT_MAX * GP];
    float xbuf[2][BT_MAX];
    float xw[4 * HP];       // decoder extra gate rows 256..259 (65 weights each)
    float xwih[4];
    float xbias[4];
    float linW[HP];
};

__device__ __forceinline__ float sigf(float x) {
    return __fdividef(1.0f, 1.0f + __expf(-x));
}

__device__ __forceinline__ float tanh_fast(float x) {
    float ax = fminf(fabsf(x), 15.0f);
    float e  = __expf(2.0f * ax);
    float t  = 1.0f - __fdividef(2.0f, e + 1.0f);
    return copysignf(t, x);
}

template <int H, int NB>
__device__ __forceinline__ void gate_block(
    Smem& sm, const float* xs, int b,
    const float4* wq, float wrem, float wih_g, float bias_g, int tid)
{
    constexpr int NQ = H / 4;
    float acc[NB];
    const float4* hr[NB];
#pragma unroll
    for (int u = 0; u < NB; u++) {
        acc[u] = fmaf(wih_g, xs[b + u], bias_g);
        hr[u]  = (const float4*)(sm.h + (b + u) * HP);
    }
#pragma unroll
    for (int q = 0; q < NQ; q++) {
#pragma unroll
        for (int u = 0; u < NB; u++) {
            float4 h4 = hr[u][q];   // warp-uniform address -> broadcast LDS
            acc[u] = fmaf(wq[q].x, h4.x, acc[u]);
            acc[u] = fmaf(wq[q].y, h4.y, acc[u]);
            acc[u] = fmaf(wq[q].z, h4.z, acc[u]);
            acc[u] = fmaf(wq[q].w, h4.w, acc[u]);
        }
    }
    if constexpr ((H % 4) != 0) {
#pragma unroll
        for (int u = 0; u < NB; u++)
            acc[u] = fmaf(wrem, sm.h[(b + u) * HP + H - 1], acc[u]);
    }
#pragma unroll
    for (int u = 0; u < NB; u++)
        sm.gates[(b + u) * GP + tid] = acc[u];
}

template <int H, bool IS_DEC>
__device__ __forceinline__ void lstm_scan(
    Smem& sm, int bt, int b0,
    const float* __restrict__ xglob,   // enc: input_batch ; dec: target_batch (shifted)
    const float* __restrict__ Wih,
    const float* __restrict__ Whh,
    const float* __restrict__ bih,
    const float* __restrict__ bhh,
    float* __restrict__ out,
    float linb)
{
    constexpr int NQ = H / 4;
    const int tid  = threadIdx.x;
    const int wid  = tid >> 5;
    const int lane = tid & 31;

    // ---- load my gate row into registers (all 256 threads own a gate) ----
    float4 wq[NQ];
    float  wrem = 0.0f;
    float  wih_g, bias_g;
    {
        const int g = tid;                 // gate index; NG >= 256 always
        const float* wr = Whh + g * H;
#pragma unroll
        for (int q = 0; q < NQ; q++)
            wq[q] = make_float4(wr[4 * q], wr[4 * q + 1], wr[4 * q + 2], wr[4 * q + 3]);
        if constexpr ((H % 4) != 0) wrem = wr[H - 1];
        wih_g  = Wih[g];
        bias_g = bih[g] + bhh[g];
    }

    // ---- precompute pointwise-update mapping (fixed across time steps) ----
    // element p = tid + k*NTHREADS  ->  (b = p/H, j = p%H), p < H*bt
    int   ucnt = 0;
    int   ub[4], uj[4];
    {
        const int npairs = H * bt;
        for (int p = tid; p < npairs; p += NTHREADS) {
            ub[ucnt] = p / H;
            uj[ucnt] = p - ub[ucnt] * H;
            ucnt++;
        }
    }

    for (int t = 0; t < T_STEPS; t++) {
        // ---- issue next-step input load early (consumed after gate phase) ----
        float xnext = 0.0f;
        const bool do_pref = (tid < bt) && (t + 1 < T_STEPS);
        if (do_pref) {
            const int row = IS_DEC ? t : (t + 1);   // dec x[t+1] = target[t]
            xnext = xglob[row * BATCH + b0 + tid];
        }
        const float* xs = sm.xbuf[t & 1];

        // ---- gate phase: acc_g = bias + wih*x + sum_k Whh[g][k]*h[b][k] ----
        {
            int b = 0;
            for (; b + 4 <= bt; b += 4)
                gate_block<H, 4>(sm, xs, b, wq, wrem, wih_g, bias_g, tid);
            const int rem = bt - b;
            if (rem == 1)      gate_block<H, 1>(sm, xs, b, wq, wrem, wih_g, bias_g, tid);
            else if (rem == 2) gate_block<H, 2>(sm, xs, b, wq, wrem, wih_g, bias_g, tid);
            else if (rem == 3) gate_block<H, 3>(sm, xs, b, wq, wrem, wih_g, bias_g, tid);
        }

        // ---- decoder: 4 leftover o-gate rows (256..259), warp-cooperative ----
        if constexpr (IS_DEC) {
            const int ntask = 4 * bt;
            for (int task = wid; task < ntask; task += NWARPS) {
                const int e = task & 3;
                const int b = task >> 2;
                const float* w    = sm.xw + e * HP;
                const float* hrow = sm.h + b * HP;
                float p = w[lane] * hrow[lane] + w[lane + 32] * hrow[lane + 32];
                if (lane == 0) p += w[64] * hrow[64];
#pragma unroll
                for (int off = 16; off; off >>= 1)
                    p += __shfl_down_sync(0xffffffffu, p, off);
                if (lane == 0)
                    sm.gates[b * GP + 256 + e] =
                        sm.xbias[e] + sm.xwih[e] * xs[b] + p;
            }
        }

        if (do_pref) sm.xbuf[(t + 1) & 1][tid] = xnext;
        __syncthreads();

        // ---- pointwise LSTM update (precomputed (b,j) mapping) ----
#pragma unroll
        for (int k = 0; k < 4; k++) {
            if (k < ucnt) {
                const int b = ub[k];
                const int j = uj[k];
                const float* gr = sm.gates + b * GP;
                const float gi = gr[j];
                const float gf = gr[H + j];
                const float gg = gr[2 * H + j];
                const float go = gr[3 * H + j];
                float c  = sm.c[b * HP + j];
                float cn = sigf(gf) * c + sigf(gi) * tanh_fast(gg);
                sm.c[b * HP + j] = cn;
                sm.h[b * HP + j] = sigf(go) * tanh_fast(cn);
            }
        }
        __syncthreads();

        // ---- decoder: output projection out[t,b] = lin_W . h + lin_b ----
        if constexpr (IS_DEC) {
            for (int b = wid; b < bt; b += NWARPS) {
                const float* hrow = sm.h + b * HP;
                float p = sm.linW[lane] * hrow[lane]
                        + sm.linW[lane + 32] * hrow[lane + 32];
                if (lane == 0) p += sm.linW[64] * hrow[64];
#pragma unroll
                for (int off = 16; off; off >>= 1)
                    p += __shfl_down_sync(0xffffffffu, p, off);
                if (lane == 0)
                    out[t * BATCH + b0 + b] = p + linb;
            }
        }
    }
}

__global__ void __launch_bounds__(NTHREADS, 1)
lstm_seq2seq_kernel(
    const float* __restrict__ input,  const float* __restrict__ speed,
    const float* __restrict__ target,
    const float* __restrict__ eWih,   const float* __restrict__ eWhh,
    const float* __restrict__ ebih,   const float* __restrict__ ebhh,
    const float* __restrict__ dWih,   const float* __restrict__ dWhh,
    const float* __restrict__ dbih,   const float* __restrict__ dbhh,
    const float* __restrict__ linW,   const float* __restrict__ linb,
    const float* __restrict__ denseW, const float* __restrict__ denseb,
    float* __restrict__ out)
{
    __shared__ Smem sm;
    const int tid  = threadIdx.x;
    const int cta  = blockIdx.x;
    const int base = BATCH / NCTA;     // 13
    const int rem  = BATCH % NCTA;     // 124
    const int bt   = base + (cta < rem ? 1 : 0);
    const int b0   = cta * base + min(cta, rem);

    // ---- init shared state ----
    for (int i = tid; i < BT_MAX * HP; i += NTHREADS) {
        sm.h[i] = 0.0f;
        sm.c[i] = 0.0f;
    }
    for (int i = tid; i < 4 * 65; i += NTHREADS) {
        const int e = i / 65, k = i - e * 65;
        sm.xw[e * HP + k] = dWhh[(256 + e) * 65 + k];
    }
    if (tid < 4) {
        sm.xwih[tid]  = dWih[256 + tid];
        sm.xbias[tid] = dbih[256 + tid] + dbhh[256 + tid];
    }
    for (int i = tid; i < 65; i += NTHREADS) sm.linW[i] = linW[i];
    if (tid < bt) sm.xbuf[0][tid] = input[b0 + tid];   // x at t=0
    const float lb = linb[0];
    __syncthreads();

    // ---- encoder scan (H=64) ----
    lstm_scan<64, false>(sm, bt, b0, input, eWih, eWhh, ebih, ebhh, nullptr, 0.0f);

    // ---- transition: append Dense(speed) to hidden & cell, zero dec x0 ----
    if (tid < bt) {
        const float sp = denseb[0] + denseW[0] * speed[b0 + tid];
        sm.h[tid * HP + 64] = sp;
        sm.c[tid * HP + 64] = sp;
        sm.xbuf[0][tid] = 0.0f;        // teacher forcing: x_dec[0] = 0
    }
    __syncthreads();

    // ---- decoder scan (H=65) + output projection ----
    lstm_scan<65, true>(sm, bt, b0, target, dWih, dWhh, dbih, dbhh, out, lb);
}

extern "C" void kernel_launch(void* const* d_in, const int* in_sizes, int n_in,
                              void* d_out, int out_size)
{
    const float* input  = (const float*)d_in[0];
    const float* speed  = (const float*)d_in[1];
    const float* target = (const float*)d_in[2];
    const float* eWih   = (const float*)d_in[3];
    const float* eWhh   = (const float*)d_in[4];
    const float* ebih   = (const float*)d_in[5];
    const float* ebhh   = (const float*)d_in[6];
    const float* dWih   = (const float*)d_in[7];
    const float* dWhh   = (const float*)d_in[8];
    const float* dbih   = (const float*)d_in[9];
    const float* dbhh   = (const float*)d_in[10];
    const float* linW   = (const float*)d_in[11];
    const float* linb   = (const float*)d_in[12];
    const float* denseW = (const float*)d_in[13];
    const float* denseb = (const float*)d_in[14];
    float* out = (float*)d_out;

    lstm_seq2seq_kernel<<<NCTA, NTHREADS>>>(
        input, speed, target,
        eWih, eWhh, ebih, ebhh,
        dWih, dWhh, dbih, dbhh,
        linW, linb, denseW, denseb, out);
}

// round 3
// speedup vs baseline: 1.3518x; 1.3518x over previous
#include <cuda_runtime.h>

// LSTM seq2seq: encoder (1->64) over T=1000, decoder (1->65) with teacher
// forcing over T=1000, output Linear(65->1). B=2048.
//
// Round 3: 2 CTAs/SM (296 CTAs, bt<=7) for 25% occupancy, and the gate
// phase packed with fma.rn.f32x2 (2 MACs/instr). Thread t owns gate row t
// (weights in packed registers). h/c in shared; per step: gate phase,
// barrier, pointwise update, barrier, projection.

#define T_STEPS   1000
#define BATCH     2048
#define NCTA      296
#define NTHREADS  256
#define NWARPS    (NTHREADS / 32)
#define BT_MAX    7
#define HP        68     // h/c row pitch (floats), 16B-aligned rows
#define GP        264    // gates row pitch (floats)

typedef unsigned long long u64;

struct Smem {
    float h[BT_MAX * HP];
    float c[BT_MAX * HP];
    float gates[BT_MAX * GP];
    float xbuf[2][BT_MAX];
    float xw[4 * HP];       // decoder extra gate rows 256..259 (65 weights each)
    float xwih[4];
    float xbias[4];
    float linW[HP];
};

__device__ __forceinline__ u64 pack2(float lo, float hi) {
    u64 r;
    asm("mov.b64 %0, {%1, %2};" : "=l"(r) : "f"(lo), "f"(hi));
    return r;
}
__device__ __forceinline__ float2 unpack2(u64 v) {
    float lo, hi;
    asm("mov.b64 {%0, %1}, %2;" : "=f"(lo), "=f"(hi) : "l"(v));
    return make_float2(lo, hi);
}
__device__ __forceinline__ void ffma2(u64& d, u64 a, u64 b, u64 c) {
    asm("fma.rn.f32x2 %0, %1, %2, %3;" : "=l"(d) : "l"(a), "l"(b), "l"(c));
}

__device__ __forceinline__ float sigf(float x) {
    return __fdividef(1.0f, 1.0f + __expf(-x));
}

__device__ __forceinline__ float tanh_fast(float x) {
    float ax = fminf(fabsf(x), 15.0f);
    float e  = __expf(2.0f * ax);
    float t  = 1.0f - __fdividef(2.0f, e + 1.0f);
    return copysignf(t, x);
}

// Gate dot product for NB batch rows, packed f32x2.
// NQ = H/4 float4 chunks (covers k = 0..4*NQ-1); remainder handled by caller.
template <int H, int NB>
__device__ __forceinline__ void gate_block(
    Smem& sm, const float* xs, int b,
    const u64* w2, float wrem, float wih_g, float bias_g, int tid)
{
    constexpr int NQ = H / 4;
    u64 acc2[NB];
    const ulonglong2* hr[NB];
#pragma unroll
    for (int u = 0; u < NB; u++) {
        acc2[u] = pack2(fmaf(wih_g, xs[b + u], bias_g), 0.0f);
        hr[u]   = (const ulonglong2*)(sm.h + (b + u) * HP);
    }
#pragma unroll
    for (int q = 0; q < NQ; q++) {
#pragma unroll
        for (int u = 0; u < NB; u++) {
            ulonglong2 h2 = hr[u][q];   // warp-uniform address -> broadcast LDS.128
            ffma2(acc2[u], w2[2 * q],     h2.x, acc2[u]);
            ffma2(acc2[u], w2[2 * q + 1], h2.y, acc2[u]);
        }
    }
#pragma unroll
    for (int u = 0; u < NB; u++) {
        float2 a = unpack2(acc2[u]);
        float acc = a.x + a.y;
        if constexpr ((H % 4) != 0)
            acc = fmaf(wrem, sm.h[(b + u) * HP + H - 1], acc);
        sm.gates[(b + u) * GP + tid] = acc;
    }
}

template <int H, bool IS_DEC>
__device__ __forceinline__ void lstm_scan(
    Smem& sm, int bt, int b0,
    const float* __restrict__ xglob,   // enc: input_batch ; dec: target_batch (shifted)
    const float* __restrict__ Wih,
    const float* __restrict__ Whh,
    const float* __restrict__ bih,
    const float* __restrict__ bhh,
    float* __restrict__ out,
    float linb)
{
    constexpr int NPAIR = H / 2;       // 32 for both H=64 and H=65 (floor)
    const int tid  = threadIdx.x;
    const int wid  = tid >> 5;
    const int lane = tid & 31;

    // ---- load my gate row into packed registers ----
    u64   w2[NPAIR];
    float wrem = 0.0f;
    float wih_g, bias_g;
    {
        const int g = tid;
        const float* wr = Whh + g * H;
#pragma unroll
        for (int p = 0; p < NPAIR; p++)
            w2[p] = pack2(wr[2 * p], wr[2 * p + 1]);
        if constexpr ((H % 4) != 0) wrem = wr[H - 1];
        wih_g  = Wih[g];
        bias_g = bih[g] + bhh[g];
    }

    // ---- precompute pointwise-update mapping (fixed across time steps) ----
    int ucnt = 0;
    int ub[2], uj[2];
    {
        const int npairs = H * bt;      // <= 65*7 = 455 < 2*NTHREADS
        for (int p = tid; p < npairs; p += NTHREADS) {
            ub[ucnt] = p / H;
            uj[ucnt] = p - ub[ucnt] * H;
            ucnt++;
        }
    }

    for (int t = 0; t < T_STEPS; t++) {
        // ---- issue next-step input load early (consumed after gate phase) ----
        float xnext = 0.0f;
        const bool do_pref = (tid < bt) && (t + 1 < T_STEPS);
        if (do_pref) {
            const int row = IS_DEC ? t : (t + 1);   // dec x[t+1] = target[t]
            xnext = xglob[row * BATCH + b0 + tid];
        }
        const float* xs = sm.xbuf[t & 1];

        // ---- gate phase ----
        {
            int b = 0;
            for (; b + 4 <= bt; b += 4)
                gate_block<H, 4>(sm, xs, b, w2, wrem, wih_g, bias_g, tid);
            const int rem = bt - b;
            if (rem == 1)      gate_block<H, 1>(sm, xs, b, w2, wrem, wih_g, bias_g, tid);
            else if (rem == 2) gate_block<H, 2>(sm, xs, b, w2, wrem, wih_g, bias_g, tid);
            else if (rem == 3) gate_block<H, 3>(sm, xs, b, w2, wrem, wih_g, bias_g, tid);
        }

        // ---- decoder: 4 leftover o-gate rows (256..259), warp-cooperative ----
        if constexpr (IS_DEC) {
            const int ntask = 4 * bt;
            for (int task = wid; task < ntask; task += NWARPS) {
                const int e = task & 3;
                const int b = task >> 2;
                const float* w    = sm.xw + e * HP;
                const float* hrow = sm.h + b * HP;
                float p = w[lane] * hrow[lane] + w[lane + 32] * hrow[lane + 32];
                if (lane == 0) p += w[64] * hrow[64];
#pragma unroll
                for (int off = 16; off; off >>= 1)
                    p += __shfl_down_sync(0xffffffffu, p, off);
                if (lane == 0)
                    sm.gates[b * GP + 256 + e] =
                        sm.xbias[e] + sm.xwih[e] * xs[b] + p;
            }
        }

        if (do_pref) sm.xbuf[(t + 1) & 1][tid] = xnext;
        __syncthreads();

        // ---- pointwise LSTM update (precomputed (b,j) mapping) ----
#pragma unroll
        for (int k = 0; k < 2; k++) {
            if (k < ucnt) {
                const int b = ub[k];
                const int j = uj[k];
                const float* gr = sm.gates + b * GP;
                const float gi = gr[j];
                const float gf = gr[H + j];
                const float gg = gr[2 * H + j];
                const float go = gr[3 * H + j];
                float c  = sm.c[b * HP + j];
                float cn = sigf(gf) * c + sigf(gi) * tanh_fast(gg);
                sm.c[b * HP + j] = cn;
                sm.h[b * HP + j] = sigf(go) * tanh_fast(cn);
            }
        }
        __syncthreads();

        // ---- decoder: output projection out[t,b] = lin_W . h + lin_b ----
        if constexpr (IS_DEC) {
            for (int b = wid; b < bt; b += NWARPS) {
                const float* hrow = sm.h + b * HP;
                float p = sm.linW[lane] * hrow[lane]
                        + sm.linW[lane + 32] * hrow[lane + 32];
                if (lane == 0) p += sm.linW[64] * hrow[64];
#pragma unroll
                for (int off = 16; off; off >>= 1)
                    p += __shfl_down_sync(0xffffffffu, p, off);
                if (lane == 0)
                    out[t * BATCH + b0 + b] = p + linb;
            }
        }
    }
}

__global__ void __launch_bounds__(NTHREADS, 2)
lstm_seq2seq_kernel(
    const float* __restrict__ input,  const float* __restrict__ speed,
    const float* __restrict__ target,
    const float* __restrict__ eWih,   const float* __restrict__ eWhh,
    const float* __restrict__ ebih,   const float* __restrict__ ebhh,
    const float* __restrict__ dWih,   const float* __restrict__ dWhh,
    const float* __restrict__ dbih,   const float* __restrict__ dbhh,
    const float* __restrict__ linW,   const float* __restrict__ linb,
    const float* __restrict__ denseW, const float* __restrict__ denseb,
    float* __restrict__ out)
{
    __shared__ Smem sm;
    const int tid  = threadIdx.x;
    const int cta  = blockIdx.x;
    const int base = BATCH / NCTA;     // 6
    const int rem  = BATCH % NCTA;     // 272
    const int bt   = base + (cta < rem ? 1 : 0);
    const int b0   = cta * base + min(cta, rem);

    // ---- init shared state ----
    for (int i = tid; i < BT_MAX * HP; i += NTHREADS) {
        sm.h[i] = 0.0f;
        sm.c[i] = 0.0f;
    }
    for (int i = tid; i < 4 * 65; i += NTHREADS) {
        const int e = i / 65, k = i - e * 65;
        sm.xw[e * HP + k] = dWhh[(256 + e) * 65 + k];
    }
    if (tid < 4) {
        sm.xwih[tid]  = dWih[256 + tid];
        sm.xbias[tid] = dbih[256 + tid] + dbhh[256 + tid];
    }
    for (int i = tid; i < 65; i += NTHREADS) sm.linW[i] = linW[i];
    if (tid < bt) sm.xbuf[0][tid] = input[b0 + tid];   // x at t=0
    const float lb = linb[0];
    __syncthreads();

    // ---- encoder scan (H=64) ----
    lstm_scan<64, false>(sm, bt, b0, input, eWih, eWhh, ebih, ebhh, nullptr, 0.0f);

    // ---- transition: append Dense(speed) to hidden & cell, zero dec x0 ----
    if (tid < bt) {
        const float sp = denseb[0] + denseW[0] * speed[b0 + tid];
        sm.h[tid * HP + 64] = sp;
        sm.c[tid * HP + 64] = sp;
        sm.xbuf[0][tid] = 0.0f;        // teacher forcing: x_dec[0] = 0
    }
    __syncthreads();

    // ---- decoder scan (H=65) + output projection ----
    lstm_scan<65, true>(sm, bt, b0, target, dWih, dWhh, dbih, dbhh, out, lb);
}

extern "C" void kernel_launch(void* const* d_in, const int* in_sizes, int n_in,
                              void* d_out, int out_size)
{
    const float* input  = (const float*)d_in[0];
    const float* speed  = (const float*)d_in[1];
    const float* target = (const float*)d_in[2];
    const float* eWih   = (const float*)d_in[3];
    const float* eWhh   = (const float*)d_in[4];
    const float* ebih   = (const float*)d_in[5];
    const float* ebhh   = (const float*)d_in[6];
    const float* dWih   = (const float*)d_in[7];
    const float* dWhh   = (const float*)d_in[8];
    const float* dbih   = (const float*)d_in[9];
    const float* dbhh   = (const float*)d_in[10];
    const float* linW   = (const float*)d_in[11];
    const float* linb   = (const float*)d_in[12];
    const float* denseW = (const float*)d_in[13];
    const float* denseb = (const float*)d_in[14];
    float* out = (float*)d_out;

    lstm_seq2seq_kernel<<<NCTA, NTHREADS>>>(
        input, speed, target,
        eWih, eWhh, ebih, ebhh,
        dWih, dWhh, dbih, dbhh,
        linW, linb, denseW, denseb, out);
}

// round 4
// speedup vs baseline: 1.4665x; 1.0848x over previous
#include <cuda_runtime.h>

// LSTM seq2seq: encoder (1->64) over T=1000, decoder (1->65) with teacher
// forcing over T=1000, output Linear(65->1). B=2048.
//
// Round 4: gate phase restructured for 2x LDS reuse. Thread t = (pair, half)
// owns gate rows {2p, 2p+1} on k-half [32*half, 32*half+32): each h chunk
// loaded feeds 4 FFMA2 instead of 2. Partials combined across the k-halves
// with one shfl_xor(1); thread t finalizes gate row t. h rows stored split
// (cols 0..31 at +0, cols 32..64 at +36) so the two half-groups hit
// disjoint banks in every LDS.128.

#define T_STEPS   1000
#define BATCH     2048
#define NCTA      296
#define NTHREADS  256
#define NWARPS    (NTHREADS / 32)
#define BT_MAX    7
#define HP        72     // h/c row pitch (floats); h split: [0..31]=cols0-31, [36..68]=cols32-64
#define GP        264    // gates row pitch (floats)

typedef unsigned long long u64;

struct Smem {
    float h[BT_MAX * HP];   // split layout (see above)
    float c[BT_MAX * HP];   // linear layout (j = 0..H-1)
    float gates[BT_MAX * GP];
    float xbuf[2][BT_MAX];
    float xw[4 * HP];       // decoder extra gate rows 256..259, linear (65 weights)
    float xwih[4];
    float xbias[4];
    float linW[HP];         // linear
};

__device__ __forceinline__ u64 pack2(float lo, float hi) {
    u64 r;
    asm("mov.b64 %0, {%1, %2};" : "=l"(r) : "f"(lo), "f"(hi));
    return r;
}
__device__ __forceinline__ float2 unpack2(u64 v) {
    float lo, hi;
    asm("mov.b64 {%0, %1}, %2;" : "=f"(lo), "=f"(hi) : "l"(v));
    return make_float2(lo, hi);
}
__device__ __forceinline__ void ffma2(u64& d, u64 a, u64 b, u64 c) {
    asm("fma.rn.f32x2 %0, %1, %2, %3;" : "=l"(d) : "l"(a), "l"(b), "l"(c));
}

__device__ __forceinline__ float sigf(float x) {
    return __fdividef(1.0f, 1.0f + __expf(-x));
}

__device__ __forceinline__ float tanh_fast(float x) {
    float ax = fminf(fabsf(x), 15.0f);
    float e  = __expf(2.0f * ax);
    float t  = 1.0f - __fdividef(2.0f, e + 1.0f);
    return copysignf(t, x);
}

// Gate partial dot products for NB batch rows: 2 gate rows x 32-col k-half.
// w2[0..15] = row r0 pairs, w2[16..31] = row r1 pairs (this thread's k-half).
template <int H, int NB>
__device__ __forceinline__ void gate_block(
    Smem& sm, const float* xs, int b,
    const u64* w2, float wrem0, float wrem1,
    float wih_g, float bias_g, int tid, int half)
{
    u64 a0[NB], a1[NB];
    const ulonglong2* hp[NB];
#pragma unroll
    for (int u = 0; u < NB; u++) {
        a0[u] = 0ull;
        a1[u] = 0ull;
        hp[u] = (const ulonglong2*)(sm.h + (b + u) * HP + half * 36);
    }
#pragma unroll
    for (int q = 0; q < 8; q++) {
#pragma unroll
        for (int u = 0; u < NB; u++) {
            ulonglong2 h2 = hp[u][q];   // 2 disjoint-bank broadcast groups
            ffma2(a0[u], w2[2 * q],      h2.x, a0[u]);
            ffma2(a0[u], w2[2 * q + 1],  h2.y, a0[u]);
            ffma2(a1[u], w2[16 + 2 * q], h2.x, a1[u]);
            ffma2(a1[u], w2[17 + 2 * q], h2.y, a1[u]);
        }
    }
#pragma unroll
    for (int u = 0; u < NB; u++) {
        float2 s0 = unpack2(a0[u]);
        float2 s1 = unpack2(a1[u]);
        float p0 = s0.x + s0.y;
        float p1 = s1.x + s1.y;
        if constexpr (H == 65) {
            const float h64 = sm.h[(b + u) * HP + 68];
            p0 = fmaf(wrem0, h64, p0);
            p1 = fmaf(wrem1, h64, p1);
        }
        // thread (pair, half=0) finalizes row 2p (= tid); half=1 finalizes 2p+1 (= tid)
        const float send = half ? p0 : p1;
        const float recv = __shfl_xor_sync(0xffffffffu, send, 1);
        const float own  = half ? p1 : p0;
        sm.gates[(b + u) * GP + tid] = fmaf(wih_g, xs[b + u], bias_g + own + recv);
    }
}

template <int H, bool IS_DEC>
__device__ __forceinline__ void lstm_scan(
    Smem& sm, int bt, int b0,
    const float* __restrict__ xglob,
    const float* __restrict__ Wih,
    const float* __restrict__ Whh,
    const float* __restrict__ bih,
    const float* __restrict__ bhh,
    float* __restrict__ out,
    float linb)
{
    const int tid  = threadIdx.x;
    const int wid  = tid >> 5;
    const int lane = tid & 31;
    const int pair = tid >> 1;
    const int half = tid & 1;

    // ---- load weight tile: rows {2p, 2p+1}, cols [32*half, 32*half+32) ----
    u64   w2[32];
    float wrem0 = 0.0f, wrem1 = 0.0f;
    float wih_g, bias_g;
    {
        const int r0 = 2 * pair, r1 = r0 + 1;
        const float* wr0 = Whh + r0 * H + half * 32;
        const float* wr1 = Whh + r1 * H + half * 32;
#pragma unroll
        for (int p = 0; p < 16; p++) {
            w2[p]      = pack2(wr0[2 * p], wr0[2 * p + 1]);
            w2[16 + p] = pack2(wr1[2 * p], wr1[2 * p + 1]);
        }
        if constexpr (H == 65) {
            if (half) {
                wrem0 = Whh[r0 * H + 64];
                wrem1 = Whh[r1 * H + 64];
            }
        }
        wih_g  = Wih[tid];                 // finalized row = tid
        bias_g = bih[tid] + bhh[tid];
    }

    // ---- precompute pointwise-update mapping ----
    int ucnt = 0;
    int ub[2], ujc[2], ujh[2];             // batch, c-index (linear), h-index (split)
    {
        const int npairs = H * bt;
        for (int p = tid; p < npairs; p += NTHREADS) {
            const int b = p / H;
            const int j = p - b * H;
            ub[ucnt]  = b;
            ujc[ucnt] = j;
            ujh[ucnt] = (j < 32) ? j : (j + 4);
            ucnt++;
        }
    }

    for (int t = 0; t < T_STEPS; t++) {
        float xnext = 0.0f;
        const bool do_pref = (tid < bt) && (t + 1 < T_STEPS);
        if (do_pref) {
            const int row = IS_DEC ? t : (t + 1);
            xnext = xglob[row * BATCH + b0 + tid];
        }
        const float* xs = sm.xbuf[t & 1];

        // ---- gate phase ----
        {
            int b = 0;
            for (; b + 4 <= bt; b += 4)
                gate_block<H, 4>(sm, xs, b, w2, wrem0, wrem1, wih_g, bias_g, tid, half);
            const int rem = bt - b;
            if (rem == 1)      gate_block<H, 1>(sm, xs, b, w2, wrem0, wrem1, wih_g, bias_g, tid, half);
            else if (rem == 2) gate_block<H, 2>(sm, xs, b, w2, wrem0, wrem1, wih_g, bias_g, tid, half);
            else if (rem == 3) gate_block<H, 3>(sm, xs, b, w2, wrem0, wrem1, wih_g, bias_g, tid, half);
        }

        // ---- decoder: leftover gate rows 256..259, warp-cooperative ----
        if constexpr (IS_DEC) {
            const int ntask = 4 * bt;
            for (int task = wid; task < ntask; task += NWARPS) {
                const int e = task & 3;
                const int b = task >> 2;
                const float* w    = sm.xw + e * HP;
                const float* hrow = sm.h + b * HP;
                float p = w[lane] * hrow[lane] + w[lane + 32] * hrow[36 + lane];
                if (lane == 0) p += w[64] * hrow[68];
#pragma unroll
                for (int off = 16; off; off >>= 1)
                    p += __shfl_down_sync(0xffffffffu, p, off);
                if (lane == 0)
                    sm.gates[b * GP + 256 + e] =
                        sm.xbias[e] + sm.xwih[e] * xs[b] + p;
            }
        }

        if (do_pref) sm.xbuf[(t + 1) & 1][tid] = xnext;
        __syncthreads();

        // ---- pointwise LSTM update ----
#pragma unroll
        for (int k = 0; k < 2; k++) {
            if (k < ucnt) {
                const int b = ub[k];
                const int j = ujc[k];
                const float* gr = sm.gates + b * GP;
                const float gi = gr[j];
                const float gf = gr[H + j];
                const float gg = gr[2 * H + j];
                const float go = gr[3 * H + j];
                float c  = sm.c[b * HP + j];
                float cn = sigf(gf) * c + sigf(gi) * tanh_fast(gg);
                sm.c[b * HP + j]      = cn;
                sm.h[b * HP + ujh[k]] = sigf(go) * tanh_fast(cn);
            }
        }
        __syncthreads();

        // ---- decoder: output projection ----
        if constexpr (IS_DEC) {
            for (int b = wid; b < bt; b += NWARPS) {
                const float* hrow = sm.h + b * HP;
                float p = sm.linW[lane] * hrow[lane]
                        + sm.linW[lane + 32] * hrow[36 + lane];
                if (lane == 0) p += sm.linW[64] * hrow[68];
#pragma unroll
                for (int off = 16; off; off >>= 1)
                    p += __shfl_down_sync(0xffffffffu, p, off);
                if (lane == 0)
                    out[t * BATCH + b0 + b] = p + linb;
            }
        }
    }
}

__global__ void __launch_bounds__(NTHREADS, 2)
lstm_seq2seq_kernel(
    const float* __restrict__ input,  const float* __restrict__ speed,
    const float* __restrict__ target,
    const float* __restrict__ eWih,   const float* __restrict__ eWhh,
    const float* __restrict__ ebih,   const float* __restrict__ ebhh,
    const float* __restrict__ dWih,   const float* __restrict__ dWhh,
    const float* __restrict__ dbih,   const float* __restrict__ dbhh,
    const float* __restrict__ linW,   const float* __restrict__ linb,
    const float* __restrict__ denseW, const float* __restrict__ denseb,
    float* __restrict__ out)
{
    __shared__ Smem sm;
    const int tid  = threadIdx.x;
    const int cta  = blockIdx.x;
    const int base = BATCH / NCTA;     // 6
    const int rem  = BATCH % NCTA;     // 272
    const int bt   = base + (cta < rem ? 1 : 0);
    const int b0   = cta * base + min(cta, rem);

    for (int i = tid; i < BT_MAX * HP; i += NTHREADS) {
        sm.h[i] = 0.0f;
        sm.c[i] = 0.0f;
    }
    for (int i = tid; i < 4 * 65; i += NTHREADS) {
        const int e = i / 65, k = i - e * 65;
        sm.xw[e * HP + k] = dWhh[(256 + e) * 65 + k];
    }
    if (tid < 4) {
        sm.xwih[tid]  = dWih[256 + tid];
        sm.xbias[tid] = dbih[256 + tid] + dbhh[256 + tid];
    }
    for (int i = tid; i < 65; i += NTHREADS) sm.linW[i] = linW[i];
    if (tid < bt) sm.xbuf[0][tid] = input[b0 + tid];
    const float lb = linb[0];
    __syncthreads();

    // ---- encoder scan (H=64) ----
    lstm_scan<64, false>(sm, bt, b0, input, eWih, eWhh, ebih, ebhh, nullptr, 0.0f);

    // ---- transition: append Dense(speed) to hidden & cell, zero dec x0 ----
    if (tid < bt) {
        const float sp = denseb[0] + denseW[0] * speed[b0 + tid];
        sm.h[tid * HP + 68] = sp;      // h split layout: col 64 at +68
        sm.c[tid * HP + 64] = sp;      // c linear
        sm.xbuf[0][tid] = 0.0f;
    }
    __syncthreads();

    // ---- decoder scan (H=65) + output projection ----
    lstm_scan<65, true>(sm, bt, b0, target, dWih, dWhh, dbih, dbhh, out, lb);
}

extern "C" void kernel_launch(void* const* d_in, const int* in_sizes, int n_in,
                              void* d_out, int out_size)
{
    const float* input  = (const float*)d_in[0];
    const float* speed  = (const float*)d_in[1];
    const float* target = (const float*)d_in[2];
    const float* eWih   = (const float*)d_in[3];
    const float* eWhh   = (const float*)d_in[4];
    const float* ebih   = (const float*)d_in[5];
    const float* ebhh   = (const float*)d_in[6];
    const float* dWih   = (const float*)d_in[7];
    const float* dWhh   = (const float*)d_in[8];
    const float* dbih   = (const float*)d_in[9];
    const float* dbhh   = (const float*)d_in[10];
    const float* linW   = (const float*)d_in[11];
    const float* linb   = (const float*)d_in[12];
    const float* denseW = (const float*)d_in[13];
    const float* denseb = (const float*)d_in[14];
    float* out = (float*)d_out;

    lstm_seq2seq_kernel<<<NCTA, NTHREADS>>>(
        input, speed, target,
        eWih, eWhh, ebih, ebhh,
        dWih, dWhh, dbih, dbhh,
        linW, linb, denseW, denseb, out);
}